// round 15
// baseline (speedup 1.0000x reference)
#include <cuda_runtime.h>
#include <math.h>

#define TOPK     1024
#define DFEAT    32
#define HBINS    4096          // top-12-bit histogram
#define CAND_G   4096
#define EQ_CAP   1024
#define MAXB     256
#define CPS      8             // histogram CTAs per segment
#define CPC      4             // compaction CTAs per segment
#define GPS      4             // gather CTAs per segment

__device__ unsigned g_keys[4000000];
// layout: hist[MAXB*HBINS] | nsel[MAXB] | ncand[MAXB] | gdone[MAXB]
__device__ unsigned g_work[MAXB * HBINS + 3 * MAXB];
__device__ unsigned g_thresh[MAXB * 2];        // (D, kk) per segment
__device__ int      g_sel[MAXB * TOPK];
__device__ int      g_nseltot[MAXB];
__device__ unsigned g_candKey[MAXB * CAND_G];
__device__ int      g_candIdx[MAXB * CAND_G];
__device__ float    g_part[MAXB * GPS * DFEAT];

// ---------------------------------------------------------------------------
// Kernel 1: score (measured 64.4us @ 82.9% DRAM = at the LTS cap). Unchanged.
// ---------------------------------------------------------------------------
__global__ void score_kernel(const float* __restrict__ x,
                             const float* __restrict__ w,
                             const float* __restrict__ b,
                             unsigned* __restrict__ keys,
                             int npts, int q)     // q = ceil(npts/4)
{
    const int t = blockIdx.x * blockDim.x + threadIdx.x;
    const int point = t >> 3;
    const int lane8 = t & 7;
    if (point >= q) return;

    const int p1 = point + q;
    const int p2 = point + 2 * q;
    const int p3 = point + 3 * q;
    const bool h1 = (p1 < npts), h2 = (p2 < npts), h3 = (p3 < npts);

    const float4 wv = __ldg((const float4*)w + lane8);
    const float4 x0 = __ldg((const float4*)(x + (size_t)point * DFEAT) + lane8);
    float4 x1 = make_float4(0.f, 0.f, 0.f, 0.f);
    float4 x2 = make_float4(0.f, 0.f, 0.f, 0.f);
    float4 x3 = make_float4(0.f, 0.f, 0.f, 0.f);
    if (h1) x1 = __ldg((const float4*)(x + (size_t)p1 * DFEAT) + lane8);
    if (h2) x2 = __ldg((const float4*)(x + (size_t)p2 * DFEAT) + lane8);
    if (h3) x3 = __ldg((const float4*)(x + (size_t)p3 * DFEAT) + lane8);

    float s0 = x0.x * wv.x + x0.y * wv.y + x0.z * wv.z + x0.w * wv.w;
    float s1 = x1.x * wv.x + x1.y * wv.y + x1.z * wv.z + x1.w * wv.w;
    float s2 = x2.x * wv.x + x2.y * wv.y + x2.z * wv.z + x2.w * wv.w;
    float s3 = x3.x * wv.x + x3.y * wv.y + x3.z * wv.z + x3.w * wv.w;

#pragma unroll
    for (int o = 1; o <= 4; o <<= 1) {
        s0 += __shfl_xor_sync(0xffffffffu, s0, o);
        s1 += __shfl_xor_sync(0xffffffffu, s1, o);
        s2 += __shfl_xor_sync(0xffffffffu, s2, o);
        s3 += __shfl_xor_sync(0xffffffffu, s3, o);
    }

    if (lane8 == 0) {
        const float bb = __ldg(b);
        unsigned u0 = __float_as_uint(s0 + bb);
        keys[point] = (u0 & 0x80000000u) ? ~u0 : (u0 | 0x80000000u);
        if (h1) {
            unsigned u = __float_as_uint(s1 + bb);
            keys[p1] = (u & 0x80000000u) ? ~u : (u | 0x80000000u);
        }
        if (h2) {
            unsigned u = __float_as_uint(s2 + bb);
            keys[p2] = (u & 0x80000000u) ? ~u : (u | 0x80000000u);
        }
        if (h3) {
            unsigned u = __float_as_uint(s3 + bb);
            keys[p3] = (u & 0x80000000u) ? ~u : (u | 0x80000000u);
        }
    }
}

// ---------------------------------------------------------------------------
// Kernel 2: histogram, CPS CTAs/segment. Two half-warp smem copies halve
// intra-warp same-bin ATOMS replays (Gaussian keys -> hot exponent bins).
// ---------------------------------------------------------------------------
__global__ __launch_bounds__(1024, 1)
void hist_kernel(const unsigned* __restrict__ keys, int L)
{
    const int seg = blockIdx.x / CPS;
    const int c   = blockIdx.x % CPS;
    const unsigned* __restrict__ k = keys + (size_t)seg * L;
    unsigned* __restrict__ h = g_work + (size_t)seg * HBINS;

    __shared__ unsigned s_h[2 * HBINS];            // 32 KB
    const int tid  = threadIdx.x;
    const int half = (tid & 16) ? HBINS : 0;       // lanes 16-31 use copy 1
#pragma unroll
    for (int j = 0; j < 2 * HBINS / 1024; j++) s_h[tid + j * 1024] = 0u;
    __syncthreads();

    const int nvec = L >> 2;
    const int tail = nvec << 2;
    const int chunk = (nvec + CPS - 1) / CPS;
    const int vbeg = c * chunk;
    const int vend = min(nvec, vbeg + chunk);

#pragma unroll 4
    for (int i = vbeg + tid; i < vend; i += 1024) {
        const uint4 kv = __ldg((const uint4*)k + i);
        atomicAdd(&s_h[half + (kv.x >> 20)], 1u);
        atomicAdd(&s_h[half + (kv.y >> 20)], 1u);
        atomicAdd(&s_h[half + (kv.z >> 20)], 1u);
        atomicAdd(&s_h[half + (kv.w >> 20)], 1u);
    }
    if (c == CPS - 1) {
        for (int i = tail + tid; i < L; i += 1024)
            atomicAdd(&s_h[half + (__ldg(k + i) >> 20)], 1u);
    }
    __syncthreads();

#pragma unroll
    for (int j = 0; j < HBINS / 1024; j++) {
        const unsigned v = s_h[tid + j * 1024] + s_h[HBINS + tid + j * 1024];
        if (v) atomicAdd(&h[tid + j * 1024], v);   // RED, distinct addresses
    }
}

// ---------------------------------------------------------------------------
// Kernel 3: threshold bin per segment (parallel suffix scan). Tiny.
// ---------------------------------------------------------------------------
__global__ __launch_bounds__(1024, 1)
void thresh_kernel()
{
    const int b = blockIdx.x;
    const unsigned* __restrict__ h = g_work + (size_t)b * HBINS;

    __shared__ unsigned s_h[HBINS];
    __shared__ unsigned s_w[32];
    const int tid  = threadIdx.x;
    const int lane = tid & 31;
    const int wid  = tid >> 5;

#pragma unroll
    for (int j = 0; j < 4; j++) s_h[tid + j * 1024] = __ldg(h + tid + j * 1024);
    __syncthreads();

    const unsigned t4 = s_h[tid * 4] + s_h[tid * 4 + 1]
                      + s_h[tid * 4 + 2] + s_h[tid * 4 + 3];
    unsigned v = t4;
#pragma unroll
    for (int off = 1; off < 32; off <<= 1) {
        unsigned o = __shfl_down_sync(0xffffffffu, v, off);
        if (lane + off < 32) v += o;
    }
    if (lane == 0) s_w[wid] = v;
    __syncthreads();
    if (wid == 0) {
        const unsigned tv = s_w[lane];
        unsigned iv = tv;
#pragma unroll
        for (int off = 1; off < 32; off <<= 1) {
            unsigned o = __shfl_down_sync(0xffffffffu, iv, off);
            if (lane + off < 32) iv += o;
        }
        s_w[lane] = iv - tv;
    }
    __syncthreads();

    const long long E = (long long)s_w[wid] + (long long)(v - t4);
    long long r = (long long)TOPK - E;
    if (r >= 1 && r <= (long long)t4) {
        for (int d = tid * 4 + 3; d >= tid * 4; d--) {
            const unsigned c = s_h[d];
            if (r <= (long long)c) {
                g_thresh[2 * b] = (unsigned)d;
                g_thresh[2 * b + 1] = (unsigned)r;
                break;
            }
            r -= (long long)c;
        }
    }
}

// ---------------------------------------------------------------------------
// Kernel 4: compaction, CPC CTAs/segment -> global winner/candidate lists.
// ---------------------------------------------------------------------------
__global__ __launch_bounds__(1024, 1)
void compact_kernel(const unsigned* __restrict__ keys, int L)
{
    const int seg = blockIdx.x / CPC;
    const int c   = blockIdx.x % CPC;
    const unsigned* __restrict__ k = keys + (size_t)seg * L;
    unsigned* __restrict__ nsel  = g_work + (size_t)MAXB * HBINS;
    unsigned* __restrict__ ncand = g_work + (size_t)MAXB * HBINS + MAXB;
    int*      __restrict__ sel  = g_sel     + (size_t)seg * TOPK;
    unsigned* __restrict__ cKey = g_candKey + (size_t)seg * CAND_G;
    int*      __restrict__ cIdx = g_candIdx + (size_t)seg * CAND_G;

    const unsigned D = __ldg(&g_thresh[2 * seg]);
    const unsigned hiD  = D << 20;
    const unsigned hiD1 = hiD + (1u << 20);

    const int tid  = threadIdx.x;
    const int nvec = L >> 2;
    const int tail = nvec << 2;
    const int chunk = (nvec + CPC - 1) / CPC;
    const int vbeg = c * chunk;
    const int vend = min(nvec, vbeg + chunk);

#pragma unroll 4
    for (int i = vbeg + tid; i < vend; i += 1024) {
        const uint4 kv = __ldg((const uint4*)k + i);
        const int base = i << 2;
        const unsigned ks[4] = {kv.x, kv.y, kv.z, kv.w};
#pragma unroll
        for (int cc = 0; cc < 4; cc++) {
            const unsigned key = ks[cc];
            if (key >= hiD) {                        // RARE (~3%)
                if (key >= hiD1) {
                    const unsigned p = atomicAdd(&nsel[seg], 1u);
                    if (p < TOPK) sel[p] = base + cc;
                } else {
                    const unsigned p = atomicAdd(&ncand[seg], 1u);
                    if (p < CAND_G) { cKey[p] = key; cIdx[p] = base + cc; }
                }
            }
        }
    }
    if (c == CPC - 1) {
        for (int i = tail + tid; i < L; i += 1024) {
            const unsigned key = __ldg(k + i);
            if (key >= hiD) {
                if (key >= hiD1) {
                    const unsigned p = atomicAdd(&nsel[seg], 1u);
                    if (p < TOPK) sel[p] = i;
                } else {
                    const unsigned p = atomicAdd(&ncand[seg], 1u);
                    if (p < CAND_G) { cKey[p] = key; cIdx[p] = i; }
                }
            }
        }
    }
}

// ---------------------------------------------------------------------------
// Kernel 5: finalize selection. Parallel digit-find radix over candidates.
// ---------------------------------------------------------------------------
__global__ __launch_bounds__(1024, 1)
void final_kernel(const unsigned* __restrict__ keys, int L)
{
    const int b = blockIdx.x;
    const unsigned* __restrict__ nselg  = g_work + (size_t)MAXB * HBINS;
    const unsigned* __restrict__ ncandg = g_work + (size_t)MAXB * HBINS + MAXB;
    const unsigned* __restrict__ cKeyG = g_candKey + (size_t)b * CAND_G;
    const int*      __restrict__ cIdxG = g_candIdx + (size_t)b * CAND_G;
    const unsigned* __restrict__ k = keys + (size_t)b * L;
    int* __restrict__ sel = g_sel + (size_t)b * TOPK;

    __shared__ unsigned candKey[CAND_G];           // 16 KB
    __shared__ int      candIdx[CAND_G];           // 16 KB
    __shared__ int      eqIdx[EQ_CAP];
    __shared__ unsigned cnt[256];
    __shared__ unsigned s_w[32];
    __shared__ unsigned s_tkey, s_kk2;
    __shared__ int      s_napp, s_neq;

    const int tid  = threadIdx.x;
    const int lane = tid & 31;
    const int wid  = tid >> 5;

    const unsigned D  = g_thresh[2 * b];
    const unsigned kk = g_thresh[2 * b + 1];
    const unsigned hiD  = D << 20;
    const unsigned hiD1 = hiD + (1u << 20);
    const int n1raw = (int)nselg[b];
    const int n1 = (n1raw < TOPK) ? n1raw : TOPK;
    const int ncraw = (int)ncandg[b];
    const int nc = (ncraw < CAND_G) ? ncraw : CAND_G;
    const bool fastPath = (ncraw <= CAND_G);

    for (int j = tid; j < nc; j += 1024) {
        candKey[j] = __ldg(cKeyG + j);
        candIdx[j] = __ldg(cIdxG + j);
    }
    if (tid == 0) { s_tkey = hiD; s_kk2 = kk; s_napp = 0; s_neq = 0; }
    __syncthreads();

    // ---- 3 radix passes, parallel digit find ----
    const int shifts[3] = {12, 4, 0};
    const int widths[3] = {8, 8, 4};
    for (int p = 0; p < 3; p++) {
        const int sh = shifts[p], wd = widths[p];
        const unsigned maskAbove = ~((1u << (sh + wd)) - 1u);
        const unsigned bins = 1u << wd;
        if (tid < 256) cnt[tid] = 0u;
        __syncthreads();
        const unsigned pref = s_tkey;
        if (fastPath) {
            for (int j = tid; j < nc; j += 1024) {
                const unsigned key = candKey[j];
                if ((key & maskAbove) == pref)
                    atomicAdd(&cnt[(key >> sh) & (bins - 1u)], 1u);
            }
        } else {
            for (int i = tid; i < L; i += 1024) {
                const unsigned key = __ldg(k + i);
                if ((key & maskAbove) == pref)
                    atomicAdd(&cnt[(key >> sh) & (bins - 1u)], 1u);
            }
        }
        __syncthreads();

        const unsigned kk2in = s_kk2;
        const unsigned c = (tid < (int)bins) ? cnt[tid] : 0u;
        unsigned v = c;
#pragma unroll
        for (int off = 1; off < 32; off <<= 1) {
            unsigned o = __shfl_down_sync(0xffffffffu, v, off);
            if (lane + off < 32) v += o;
        }
        if (lane == 0) s_w[wid] = v;
        __syncthreads();
        if (wid == 0) {
            const unsigned tv = s_w[lane];
            unsigned iv = tv;
#pragma unroll
            for (int off = 1; off < 32; off <<= 1) {
                unsigned o = __shfl_down_sync(0xffffffffu, iv, off);
                if (lane + off < 32) iv += o;
            }
            s_w[lane] = iv - tv;
        }
        __syncthreads();
        if (tid < (int)bins) {
            const unsigned Sexcl = s_w[wid] + (v - c);
            if (Sexcl < kk2in && kk2in <= Sexcl + c) {
                s_tkey = pref | ((unsigned)tid << sh);
                s_kk2  = kk2in - Sexcl;
            }
        }
        __syncthreads();
    }
    const unsigned t = s_tkey;

    // ---- append > t; collect == t ----
    if (fastPath) {
        for (int j = tid; j < nc; j += 1024) {
            const unsigned key = candKey[j];
            if (key > t) {
                const int p = atomicAdd(&s_napp, 1);
                if (n1 + p < TOPK) sel[n1 + p] = candIdx[j];
            } else if (key == t) {
                const int p = atomicAdd(&s_neq, 1);
                if (p < EQ_CAP) eqIdx[p] = candIdx[j];
            }
        }
    } else {
        for (int i = tid; i < L; i += 1024) {
            const unsigned key = __ldg(k + i);
            if (key < hiD || key >= hiD1) continue;
            if (key > t) {
                const int p = atomicAdd(&s_napp, 1);
                if (n1 + p < TOPK) sel[n1 + p] = i;
            } else if (key == t) {
                const int p = atomicAdd(&s_neq, 1);
                if (p < EQ_CAP) eqIdx[p] = i;
            }
        }
    }
    __syncthreads();

    if (tid == 0) {
        int kk_t = (int)s_kk2;
        const int neq = (s_neq < EQ_CAP) ? s_neq : EQ_CAP;
        if (kk_t > neq) kk_t = neq;
        const int base = n1 + s_napp;
        for (int j = 0; j < kk_t; j++) {
            int mi = j;
            for (int m = j + 1; m < neq; m++)
                if (eqIdx[m] < eqIdx[mi]) mi = m;
            const int tmp = eqIdx[j]; eqIdx[j] = eqIdx[mi]; eqIdx[mi] = tmp;
            if (base + j < TOPK) sel[base + j] = eqIdx[j];
        }
        int total = base + kk_t;
        g_nseltot[b] = (total < TOPK) ? total : TOPK;
    }
}

// ---------------------------------------------------------------------------
// Kernel 6: gather partial sums (GPS CTAs/segment) + fused last-block
// normalize via done counter.
// ---------------------------------------------------------------------------
__global__ __launch_bounds__(256, 4)
void gather_kernel(const float* __restrict__ x,
                   float* __restrict__ out,
                   int L)
{
    const int b = blockIdx.x / GPS;
    const int c = blockIdx.x % GPS;
    const float* __restrict__ xb = x + (size_t)b * L * DFEAT;
    const int* __restrict__ sel = g_sel + (size_t)b * TOPK;
    unsigned* __restrict__ gdone = g_work + (size_t)MAXB * HBINS + 2 * MAXB;

    __shared__ float red[8][33];
    __shared__ int s_last;
    const int tid  = threadIdx.x;
    const int lane = tid & 31;
    const int wid  = tid >> 5;            // 0..7

    const int n = g_nseltot[b];
    const int span = TOPK / GPS;          // 256
    const int cbeg = c * span;
    const int jbeg = cbeg + wid * (span / 8);
    const int jend = min(n, min(jbeg + span / 8, cbeg + span));

    float a0 = 0.f, a1 = 0.f, a2 = 0.f, a3 = 0.f;
    float a4 = 0.f, a5 = 0.f, a6 = 0.f, a7 = 0.f;
    int j = jbeg;
    for (; j + 7 < jend; j += 8) {
        a0 += __ldg(xb + (size_t)__ldg(sel + j + 0) * DFEAT + lane);
        a1 += __ldg(xb + (size_t)__ldg(sel + j + 1) * DFEAT + lane);
        a2 += __ldg(xb + (size_t)__ldg(sel + j + 2) * DFEAT + lane);
        a3 += __ldg(xb + (size_t)__ldg(sel + j + 3) * DFEAT + lane);
        a4 += __ldg(xb + (size_t)__ldg(sel + j + 4) * DFEAT + lane);
        a5 += __ldg(xb + (size_t)__ldg(sel + j + 5) * DFEAT + lane);
        a6 += __ldg(xb + (size_t)__ldg(sel + j + 6) * DFEAT + lane);
        a7 += __ldg(xb + (size_t)__ldg(sel + j + 7) * DFEAT + lane);
    }
    for (; j < jend; j++)
        a0 += __ldg(xb + (size_t)__ldg(sel + j) * DFEAT + lane);
    red[wid][lane] = ((a0 + a1) + (a2 + a3)) + ((a4 + a5) + (a6 + a7));
    __syncthreads();

    if (wid == 0) {
        float v = 0.f;
#pragma unroll
        for (int ww = 0; ww < 8; ww++) v += red[ww][lane];
        g_part[((size_t)b * GPS + c) * DFEAT + lane] = v;
    }
    __threadfence();
    __syncthreads();
    if (tid == 0) s_last = (atomicAdd(&gdone[b], 1u) == GPS - 1);
    __syncthreads();
    if (!s_last) return;

    // last CTA of this segment: combine partials, /L, L2 normalize
    if (wid == 0) {
        float v = 0.f;
#pragma unroll
        for (int cc = 0; cc < GPS; cc++)
            v += __ldcg(&g_part[((size_t)b * GPS + cc) * DFEAT + lane]);
        v /= (float)L;
        float ss = v * v;
#pragma unroll
        for (int o = 16; o; o >>= 1) ss += __shfl_xor_sync(0xffffffffu, ss, o);
        const float norm = sqrtf(ss);
        out[b * DFEAT + lane] = v / fmaxf(norm, 1e-12f);
    }
}

extern "C" void kernel_launch(void* const* d_in, const int* in_sizes, int n_in,
                              void* d_out, int out_size)
{
    const float* x  = (const float*)d_in[0];   // [B*L, 32] fp32
    const float* w  = (const float*)d_in[2];   // [32]
    const float* bb = (const float*)d_in[3];   // [1]
    float* out = (float*)d_out;                // [B, 32]

    const int B = in_sizes[1];
    const int L = in_sizes[0] / (B * DFEAT);
    const int npts = B * L;
    const int q = (npts + 3) / 4;

    unsigned *keys = nullptr, *work = nullptr;
    cudaGetSymbolAddress((void**)&keys, g_keys);
    cudaGetSymbolAddress((void**)&work, g_work);

    // hist region (B*HBINS) and counters (at MAXB*HBINS offset)
    cudaMemsetAsync(work, 0, (size_t)B * HBINS * sizeof(unsigned));
    cudaMemsetAsync(work + (size_t)MAXB * HBINS, 0, 3 * MAXB * sizeof(unsigned));

    {
        const int threads = 256;
        const long long total = (long long)q * 8;
        const int grid = (int)((total + threads - 1) / threads);
        score_kernel<<<grid, threads>>>(x, w, bb, keys, npts, q);
    }
    hist_kernel<<<B * CPS, 1024>>>(keys, L);
    thresh_kernel<<<B, 1024>>>();
    compact_kernel<<<B * CPC, 1024>>>(keys, L);
    final_kernel<<<B, 1024>>>(keys, L);
    gather_kernel<<<B * GPS, 256>>>(x, out, L);
}

// round 16
// speedup vs baseline: 1.2361x; 1.2361x over previous
#include <cuda_runtime.h>
#include <math.h>

#define TOPK     1024
#define DFEAT    32
#define HBINS    4096          // top-12-bit histogram
#define CAND_G   4096
#define CAND_CTA 2048
#define EQ_CAP   1024
#define MAXB     256
#define CPS      8             // histogram CTAs per segment
#define CPC      4             // compaction CTAs per segment
#define GPS      4             // gather CTAs per segment

__device__ unsigned g_keys[4000000];
// layout: hist[MAXB*HBINS] | nsel[MAXB] | ncand[MAXB] | gdone[MAXB]
__device__ unsigned g_work[MAXB * HBINS + 3 * MAXB];
__device__ unsigned g_thresh[MAXB * 2];        // (D, kk) per segment
__device__ int      g_sel[MAXB * TOPK];
__device__ int      g_nseltot[MAXB];
__device__ unsigned g_candKey[MAXB * CAND_G];
__device__ int      g_candIdx[MAXB * CAND_G];
__device__ float    g_part[MAXB * GPS * DFEAT];

// ---------------------------------------------------------------------------
// Kernel 1: score (measured 64.4us @ 82.9% DRAM = at the LTS cap). Unchanged.
// ---------------------------------------------------------------------------
__global__ void score_kernel(const float* __restrict__ x,
                             const float* __restrict__ w,
                             const float* __restrict__ b,
                             unsigned* __restrict__ keys,
                             int npts, int q)     // q = ceil(npts/4)
{
    const int t = blockIdx.x * blockDim.x + threadIdx.x;
    const int point = t >> 3;
    const int lane8 = t & 7;
    if (point >= q) return;

    const int p1 = point + q;
    const int p2 = point + 2 * q;
    const int p3 = point + 3 * q;
    const bool h1 = (p1 < npts), h2 = (p2 < npts), h3 = (p3 < npts);

    const float4 wv = __ldg((const float4*)w + lane8);
    const float4 x0 = __ldg((const float4*)(x + (size_t)point * DFEAT) + lane8);
    float4 x1 = make_float4(0.f, 0.f, 0.f, 0.f);
    float4 x2 = make_float4(0.f, 0.f, 0.f, 0.f);
    float4 x3 = make_float4(0.f, 0.f, 0.f, 0.f);
    if (h1) x1 = __ldg((const float4*)(x + (size_t)p1 * DFEAT) + lane8);
    if (h2) x2 = __ldg((const float4*)(x + (size_t)p2 * DFEAT) + lane8);
    if (h3) x3 = __ldg((const float4*)(x + (size_t)p3 * DFEAT) + lane8);

    float s0 = x0.x * wv.x + x0.y * wv.y + x0.z * wv.z + x0.w * wv.w;
    float s1 = x1.x * wv.x + x1.y * wv.y + x1.z * wv.z + x1.w * wv.w;
    float s2 = x2.x * wv.x + x2.y * wv.y + x2.z * wv.z + x2.w * wv.w;
    float s3 = x3.x * wv.x + x3.y * wv.y + x3.z * wv.z + x3.w * wv.w;

#pragma unroll
    for (int o = 1; o <= 4; o <<= 1) {
        s0 += __shfl_xor_sync(0xffffffffu, s0, o);
        s1 += __shfl_xor_sync(0xffffffffu, s1, o);
        s2 += __shfl_xor_sync(0xffffffffu, s2, o);
        s3 += __shfl_xor_sync(0xffffffffu, s3, o);
    }

    if (lane8 == 0) {
        const float bb = __ldg(b);
        unsigned u0 = __float_as_uint(s0 + bb);
        keys[point] = (u0 & 0x80000000u) ? ~u0 : (u0 | 0x80000000u);
        if (h1) {
            unsigned u = __float_as_uint(s1 + bb);
            keys[p1] = (u & 0x80000000u) ? ~u : (u | 0x80000000u);
        }
        if (h2) {
            unsigned u = __float_as_uint(s2 + bb);
            keys[p2] = (u & 0x80000000u) ? ~u : (u | 0x80000000u);
        }
        if (h3) {
            unsigned u = __float_as_uint(s3 + bb);
            keys[p3] = (u & 0x80000000u) ? ~u : (u | 0x80000000u);
        }
    }
}

// ---------------------------------------------------------------------------
// Kernel 2: histogram, CPS CTAs/segment (R14 plain smem-atomic version).
// ---------------------------------------------------------------------------
__global__ __launch_bounds__(1024, 1)
void hist_kernel(const unsigned* __restrict__ keys, int L)
{
    const int seg = blockIdx.x / CPS;
    const int c   = blockIdx.x % CPS;
    const unsigned* __restrict__ k = keys + (size_t)seg * L;
    unsigned* __restrict__ h = g_work + (size_t)seg * HBINS;

    __shared__ unsigned s_h[HBINS];
    const int tid = threadIdx.x;
#pragma unroll
    for (int j = 0; j < HBINS / 1024; j++) s_h[tid + j * 1024] = 0u;
    __syncthreads();

    const int nvec = L >> 2;
    const int tail = nvec << 2;
    const int chunk = (nvec + CPS - 1) / CPS;
    const int vbeg = c * chunk;
    const int vend = min(nvec, vbeg + chunk);

#pragma unroll 4
    for (int i = vbeg + tid; i < vend; i += 1024) {
        const uint4 kv = __ldg((const uint4*)k + i);
        atomicAdd(&s_h[kv.x >> 20], 1u);
        atomicAdd(&s_h[kv.y >> 20], 1u);
        atomicAdd(&s_h[kv.z >> 20], 1u);
        atomicAdd(&s_h[kv.w >> 20], 1u);
    }
    if (c == CPS - 1) {
        for (int i = tail + tid; i < L; i += 1024)
            atomicAdd(&s_h[__ldg(k + i) >> 20], 1u);
    }
    __syncthreads();

#pragma unroll
    for (int j = 0; j < HBINS / 1024; j++) {
        const unsigned v = s_h[tid + j * 1024];
        if (v) atomicAdd(&h[tid + j * 1024], v);   // RED, distinct addresses
    }
}

// ---------------------------------------------------------------------------
// Kernel 3: threshold bin per segment (parallel suffix scan). Tiny.
// ---------------------------------------------------------------------------
__global__ __launch_bounds__(1024, 1)
void thresh_kernel()
{
    const int b = blockIdx.x;
    const unsigned* __restrict__ h = g_work + (size_t)b * HBINS;

    __shared__ unsigned s_h[HBINS];
    __shared__ unsigned s_w[32];
    const int tid  = threadIdx.x;
    const int lane = tid & 31;
    const int wid  = tid >> 5;

#pragma unroll
    for (int j = 0; j < 4; j++) s_h[tid + j * 1024] = __ldg(h + tid + j * 1024);
    __syncthreads();

    const unsigned t4 = s_h[tid * 4] + s_h[tid * 4 + 1]
                      + s_h[tid * 4 + 2] + s_h[tid * 4 + 3];
    unsigned v = t4;
#pragma unroll
    for (int off = 1; off < 32; off <<= 1) {
        unsigned o = __shfl_down_sync(0xffffffffu, v, off);
        if (lane + off < 32) v += o;
    }
    if (lane == 0) s_w[wid] = v;
    __syncthreads();
    if (wid == 0) {
        const unsigned tv = s_w[lane];
        unsigned iv = tv;
#pragma unroll
        for (int off = 1; off < 32; off <<= 1) {
            unsigned o = __shfl_down_sync(0xffffffffu, iv, off);
            if (lane + off < 32) iv += o;
        }
        s_w[lane] = iv - tv;
    }
    __syncthreads();

    const long long E = (long long)s_w[wid] + (long long)(v - t4);
    long long r = (long long)TOPK - E;
    if (r >= 1 && r <= (long long)t4) {
        for (int d = tid * 4 + 3; d >= tid * 4; d--) {
            const unsigned c = s_h[d];
            if (r <= (long long)c) {
                g_thresh[2 * b] = (unsigned)d;
                g_thresh[2 * b + 1] = (unsigned)r;
                break;
            }
            r -= (long long)c;
        }
    }
}

// ---------------------------------------------------------------------------
// Kernel 4: compaction, CPC CTAs/segment. SMEM-STAGED: all per-element
// counters are smem atomics; exactly 2 global atomics per CTA (range reserve).
// ---------------------------------------------------------------------------
__global__ __launch_bounds__(1024, 1)
void compact_kernel(const unsigned* __restrict__ keys, int L)
{
    const int seg = blockIdx.x / CPC;
    const int c   = blockIdx.x % CPC;
    const unsigned* __restrict__ k = keys + (size_t)seg * L;
    unsigned* __restrict__ nsel  = g_work + (size_t)MAXB * HBINS;
    unsigned* __restrict__ ncand = g_work + (size_t)MAXB * HBINS + MAXB;
    int*      __restrict__ sel  = g_sel     + (size_t)seg * TOPK;
    unsigned* __restrict__ cKey = g_candKey + (size_t)seg * CAND_G;
    int*      __restrict__ cIdx = g_candIdx + (size_t)seg * CAND_G;

    __shared__ int      wbuf[TOPK];              // winners staged
    __shared__ unsigned ckbuf[CAND_CTA];         // candidates staged
    __shared__ int      cibuf[CAND_CTA];
    __shared__ int      s_nw, s_ncd;
    __shared__ unsigned s_bw, s_bc;

    const unsigned D = __ldg(&g_thresh[2 * seg]);
    const unsigned hiD  = D << 20;
    const unsigned hiD1 = hiD + (1u << 20);

    const int tid  = threadIdx.x;
    if (tid == 0) { s_nw = 0; s_ncd = 0; }
    __syncthreads();

    const int nvec = L >> 2;
    const int tail = nvec << 2;
    const int chunk = (nvec + CPC - 1) / CPC;
    const int vbeg = c * chunk;
    const int vend = min(nvec, vbeg + chunk);

#pragma unroll 4
    for (int i = vbeg + tid; i < vend; i += 1024) {
        const uint4 kv = __ldg((const uint4*)k + i);
        const int base = i << 2;
        const unsigned ks[4] = {kv.x, kv.y, kv.z, kv.w};
#pragma unroll
        for (int cc = 0; cc < 4; cc++) {
            const unsigned key = ks[cc];
            if (key >= hiD) {                    // RARE (~3%)
                if (key >= hiD1) {
                    const int p = atomicAdd(&s_nw, 1);
                    if (p < TOPK) wbuf[p] = base + cc;
                } else {
                    const int p = atomicAdd(&s_ncd, 1);
                    if (p < CAND_CTA) { ckbuf[p] = key; cibuf[p] = base + cc; }
                }
            }
        }
    }
    if (c == CPC - 1) {
        for (int i = tail + tid; i < L; i += 1024) {
            const unsigned key = __ldg(k + i);
            if (key >= hiD) {
                if (key >= hiD1) {
                    const int p = atomicAdd(&s_nw, 1);
                    if (p < TOPK) wbuf[p] = i;
                } else {
                    const int p = atomicAdd(&s_ncd, 1);
                    if (p < CAND_CTA) { ckbuf[p] = key; cibuf[p] = i; }
                }
            }
        }
    }
    __syncthreads();

    const int nw  = (s_nw  < TOPK)     ? s_nw  : TOPK;
    const int ncd = (s_ncd < CAND_CTA) ? s_ncd : CAND_CTA;
    if (tid == 0) {
        s_bw = atomicAdd(&nsel[seg],  (unsigned)nw);    // 1 ATOMG per CTA
        s_bc = atomicAdd(&ncand[seg], (unsigned)s_ncd); // (true count for overflow detect)
    }
    __syncthreads();
    const unsigned bw = s_bw, bc = s_bc;

    for (int i = tid; i < nw; i += 1024)
        if (bw + i < TOPK) sel[bw + i] = wbuf[i];
    for (int i = tid; i < ncd; i += 1024)
        if (bc + i < CAND_G) { cKey[bc + i] = ckbuf[i]; cIdx[bc + i] = cibuf[i]; }
}

// ---------------------------------------------------------------------------
// Kernel 5: finalize selection. Parallel digit-find radix over candidates.
// ---------------------------------------------------------------------------
__global__ __launch_bounds__(1024, 1)
void final_kernel(const unsigned* __restrict__ keys, int L)
{
    const int b = blockIdx.x;
    const unsigned* __restrict__ nselg  = g_work + (size_t)MAXB * HBINS;
    const unsigned* __restrict__ ncandg = g_work + (size_t)MAXB * HBINS + MAXB;
    const unsigned* __restrict__ cKeyG = g_candKey + (size_t)b * CAND_G;
    const int*      __restrict__ cIdxG = g_candIdx + (size_t)b * CAND_G;
    const unsigned* __restrict__ k = keys + (size_t)b * L;
    int* __restrict__ sel = g_sel + (size_t)b * TOPK;

    __shared__ unsigned candKey[CAND_G];           // 16 KB
    __shared__ int      candIdx[CAND_G];           // 16 KB
    __shared__ int      eqIdx[EQ_CAP];
    __shared__ unsigned cnt[256];
    __shared__ unsigned s_w[32];
    __shared__ unsigned s_tkey, s_kk2;
    __shared__ int      s_napp, s_neq;

    const int tid  = threadIdx.x;
    const int lane = tid & 31;
    const int wid  = tid >> 5;

    const unsigned D  = g_thresh[2 * b];
    const unsigned kk = g_thresh[2 * b + 1];
    const unsigned hiD  = D << 20;
    const unsigned hiD1 = hiD + (1u << 20);
    const int n1raw = (int)nselg[b];
    const int n1 = (n1raw < TOPK) ? n1raw : TOPK;
    const int ncraw = (int)ncandg[b];
    const int nc = (ncraw < CAND_G) ? ncraw : CAND_G;
    const bool fastPath = (ncraw <= CAND_G);

    for (int j = tid; j < nc; j += 1024) {
        candKey[j] = __ldg(cKeyG + j);
        candIdx[j] = __ldg(cIdxG + j);
    }
    if (tid == 0) { s_tkey = hiD; s_kk2 = kk; s_napp = 0; s_neq = 0; }
    __syncthreads();

    // ---- 3 radix passes, parallel digit find ----
    const int shifts[3] = {12, 4, 0};
    const int widths[3] = {8, 8, 4};
    for (int p = 0; p < 3; p++) {
        const int sh = shifts[p], wd = widths[p];
        const unsigned maskAbove = ~((1u << (sh + wd)) - 1u);
        const unsigned bins = 1u << wd;
        if (tid < 256) cnt[tid] = 0u;
        __syncthreads();
        const unsigned pref = s_tkey;
        if (fastPath) {
            for (int j = tid; j < nc; j += 1024) {
                const unsigned key = candKey[j];
                if ((key & maskAbove) == pref)
                    atomicAdd(&cnt[(key >> sh) & (bins - 1u)], 1u);
            }
        } else {
            for (int i = tid; i < L; i += 1024) {
                const unsigned key = __ldg(k + i);
                if ((key & maskAbove) == pref)
                    atomicAdd(&cnt[(key >> sh) & (bins - 1u)], 1u);
            }
        }
        __syncthreads();

        const unsigned kk2in = s_kk2;
        const unsigned c = (tid < (int)bins) ? cnt[tid] : 0u;
        unsigned v = c;
#pragma unroll
        for (int off = 1; off < 32; off <<= 1) {
            unsigned o = __shfl_down_sync(0xffffffffu, v, off);
            if (lane + off < 32) v += o;
        }
        if (lane == 0) s_w[wid] = v;
        __syncthreads();
        if (wid == 0) {
            const unsigned tv = s_w[lane];
            unsigned iv = tv;
#pragma unroll
            for (int off = 1; off < 32; off <<= 1) {
                unsigned o = __shfl_down_sync(0xffffffffu, iv, off);
                if (lane + off < 32) iv += o;
            }
            s_w[lane] = iv - tv;
        }
        __syncthreads();
        if (tid < (int)bins) {
            const unsigned Sexcl = s_w[wid] + (v - c);
            if (Sexcl < kk2in && kk2in <= Sexcl + c) {
                s_tkey = pref | ((unsigned)tid << sh);
                s_kk2  = kk2in - Sexcl;
            }
        }
        __syncthreads();
    }
    const unsigned t = s_tkey;

    // ---- append > t; collect == t ----
    if (fastPath) {
        for (int j = tid; j < nc; j += 1024) {
            const unsigned key = candKey[j];
            if (key > t) {
                const int p = atomicAdd(&s_napp, 1);
                if (n1 + p < TOPK) sel[n1 + p] = candIdx[j];
            } else if (key == t) {
                const int p = atomicAdd(&s_neq, 1);
                if (p < EQ_CAP) eqIdx[p] = candIdx[j];
            }
        }
    } else {
        for (int i = tid; i < L; i += 1024) {
            const unsigned key = __ldg(k + i);
            if (key < hiD || key >= hiD1) continue;
            if (key > t) {
                const int p = atomicAdd(&s_napp, 1);
                if (n1 + p < TOPK) sel[n1 + p] = i;
            } else if (key == t) {
                const int p = atomicAdd(&s_neq, 1);
                if (p < EQ_CAP) eqIdx[p] = i;
            }
        }
    }
    __syncthreads();

    if (tid == 0) {
        int kk_t = (int)s_kk2;
        const int neq = (s_neq < EQ_CAP) ? s_neq : EQ_CAP;
        if (kk_t > neq) kk_t = neq;
        const int base = n1 + s_napp;
        for (int j = 0; j < kk_t; j++) {
            int mi = j;
            for (int m = j + 1; m < neq; m++)
                if (eqIdx[m] < eqIdx[mi]) mi = m;
            const int tmp = eqIdx[j]; eqIdx[j] = eqIdx[mi]; eqIdx[mi] = tmp;
            if (base + j < TOPK) sel[base + j] = eqIdx[j];
        }
        int total = base + kk_t;
        g_nseltot[b] = (total < TOPK) ? total : TOPK;
    }
}

// ---------------------------------------------------------------------------
// Kernel 6: gather partial sums (GPS=4 CTAs/segment) + fused last-block
// normalize via done counter.
// ---------------------------------------------------------------------------
__global__ __launch_bounds__(256, 4)
void gather_kernel(const float* __restrict__ x,
                   float* __restrict__ out,
                   int L)
{
    const int b = blockIdx.x / GPS;
    const int c = blockIdx.x % GPS;
    const float* __restrict__ xb = x + (size_t)b * L * DFEAT;
    const int* __restrict__ sel = g_sel + (size_t)b * TOPK;
    unsigned* __restrict__ gdone = g_work + (size_t)MAXB * HBINS + 2 * MAXB;

    __shared__ float red[8][33];
    __shared__ int s_last;
    const int tid  = threadIdx.x;
    const int lane = tid & 31;
    const int wid  = tid >> 5;            // 0..7

    const int n = g_nseltot[b];
    const int span = TOPK / GPS;          // 256
    const int cbeg = c * span;
    const int jbeg = cbeg + wid * (span / 8);
    const int jend = min(n, min(jbeg + span / 8, cbeg + span));

    float a0 = 0.f, a1 = 0.f, a2 = 0.f, a3 = 0.f;
    float a4 = 0.f, a5 = 0.f, a6 = 0.f, a7 = 0.f;
    int j = jbeg;
    for (; j + 7 < jend; j += 8) {
        a0 += __ldg(xb + (size_t)__ldg(sel + j + 0) * DFEAT + lane);
        a1 += __ldg(xb + (size_t)__ldg(sel + j + 1) * DFEAT + lane);
        a2 += __ldg(xb + (size_t)__ldg(sel + j + 2) * DFEAT + lane);
        a3 += __ldg(xb + (size_t)__ldg(sel + j + 3) * DFEAT + lane);
        a4 += __ldg(xb + (size_t)__ldg(sel + j + 4) * DFEAT + lane);
        a5 += __ldg(xb + (size_t)__ldg(sel + j + 5) * DFEAT + lane);
        a6 += __ldg(xb + (size_t)__ldg(sel + j + 6) * DFEAT + lane);
        a7 += __ldg(xb + (size_t)__ldg(sel + j + 7) * DFEAT + lane);
    }
    for (; j < jend; j++)
        a0 += __ldg(xb + (size_t)__ldg(sel + j) * DFEAT + lane);
    red[wid][lane] = ((a0 + a1) + (a2 + a3)) + ((a4 + a5) + (a6 + a7));
    __syncthreads();

    if (wid == 0) {
        float v = 0.f;
#pragma unroll
        for (int ww = 0; ww < 8; ww++) v += red[ww][lane];
        g_part[((size_t)b * GPS + c) * DFEAT + lane] = v;
    }
    __threadfence();
    __syncthreads();
    if (tid == 0) s_last = (atomicAdd(&gdone[b], 1u) == GPS - 1);
    __syncthreads();
    if (!s_last) return;

    if (wid == 0) {
        float v = 0.f;
#pragma unroll
        for (int cc = 0; cc < GPS; cc++)
            v += __ldcg(&g_part[((size_t)b * GPS + cc) * DFEAT + lane]);
        v /= (float)L;
        float ss = v * v;
#pragma unroll
        for (int o = 16; o; o >>= 1) ss += __shfl_xor_sync(0xffffffffu, ss, o);
        const float norm = sqrtf(ss);
        out[b * DFEAT + lane] = v / fmaxf(norm, 1e-12f);
    }
}

extern "C" void kernel_launch(void* const* d_in, const int* in_sizes, int n_in,
                              void* d_out, int out_size)
{
    const float* x  = (const float*)d_in[0];   // [B*L, 32] fp32
    const float* w  = (const float*)d_in[2];   // [32]
    const float* bb = (const float*)d_in[3];   // [1]
    float* out = (float*)d_out;                // [B, 32]

    const int B = in_sizes[1];
    const int L = in_sizes[0] / (B * DFEAT);
    const int npts = B * L;
    const int q = (npts + 3) / 4;

    unsigned *keys = nullptr, *work = nullptr;
    cudaGetSymbolAddress((void**)&keys, g_keys);
    cudaGetSymbolAddress((void**)&work, g_work);

    cudaMemsetAsync(work, 0, (size_t)B * HBINS * sizeof(unsigned));
    cudaMemsetAsync(work + (size_t)MAXB * HBINS, 0, 3 * MAXB * sizeof(unsigned));

    {
        const int threads = 256;
        const long long total = (long long)q * 8;
        const int grid = (int)((total + threads - 1) / threads);
        score_kernel<<<grid, threads>>>(x, w, bb, keys, npts, q);
    }
    hist_kernel<<<B * CPS, 1024>>>(keys, L);
    thresh_kernel<<<B, 1024>>>();
    compact_kernel<<<B * CPC, 1024>>>(keys, L);
    final_kernel<<<B, 1024>>>(keys, L);
    gather_kernel<<<B * GPS, 256>>>(x, out, L);
}